// round 5
// baseline (speedup 1.0000x reference)
#include <cuda_runtime.h>
#include <math.h>
#include <stdint.h>

// Problem constants (fixed by setup_inputs)
#define EMAX 500000
#define NEMAX 100000
#define NRMAX 1008
#define DD 128
#define KTOT 384
#define SCHUNK 2048
#define NBLK_MAX 64

// ---------- device scratch (static; no allocation allowed) ----------
__device__ __align__(16) float g_wa[KTOT];          // W @ a
__device__ float g_p[NEMAX];                        // emb[n] . wa[0:128]
__device__ float g_q[NEMAX];                        // emb[n] . wa[256:384]
__device__ float g_s[NRMAX];                        // rel[r] . wa[128:256]
__device__ float g_score[EMAX];                     // per-edge score / exp (sorted order)
__device__ int   g_cnt[NEMAX];                      // degree per head entity
__device__ int   g_off[NEMAX];                      // segment start offset
__device__ int   g_cur[NEMAX];                      // bucket cursor
__device__ int   g_blk[NBLK_MAX];                   // scan block totals
__device__ int   g_blkoff[NBLK_MAX];                // scan block offsets
__device__ int   g_eidx[EMAX];                      // edge ids bucketed by h
__device__ __align__(16) float g_acc[NEMAX * DD];   // emb@W1
__device__ __align__(16) float g_embW3[NEMAX * DD]; // emb@W3
__device__ __align__(16) float g_relW2[NRMAX * DD]; // rel@W2

// ---------- helpers ----------
__device__ __forceinline__ uint32_t f2tf(float f) {
    uint32_t r;
    asm("cvt.rna.tf32.f32 %0, %1;" : "=r"(r) : "f"(f));
    return r;
}

// ---------- small kernels ----------
__global__ void k_wa(const float* __restrict__ W, const float* __restrict__ a) {
    int k = blockIdx.x * blockDim.x + threadIdx.x;
    if (k < KTOT) {
        const float* row = W + (size_t)k * DD;
        float s = 0.f;
        #pragma unroll 8
        for (int u = 0; u < DD; u++) s = fmaf(row[u], a[u], s);
        g_wa[k] = s;
    }
}

__global__ void k_zero_cnt(int NE) {
    int i = blockIdx.x * blockDim.x + threadIdx.x;
    if (i < NE) g_cnt[i] = 0;
}

__global__ void k_entity_dots(const float* __restrict__ emb, int NE) {
    int w = (blockIdx.x * blockDim.x + threadIdx.x) >> 5;
    int lane = threadIdx.x & 31;
    if (w >= NE) return;
    float4 v   = ((const float4*)(emb + (size_t)w * DD))[lane];
    float4 wa0 = ((const float4*)g_wa)[lane];
    float4 wa2 = ((const float4*)(g_wa + 256))[lane];
    float p = v.x*wa0.x + v.y*wa0.y + v.z*wa0.z + v.w*wa0.w;
    float q = v.x*wa2.x + v.y*wa2.y + v.z*wa2.z + v.w*wa2.w;
    #pragma unroll
    for (int o = 16; o; o >>= 1) {
        p += __shfl_xor_sync(0xffffffffu, p, o);
        q += __shfl_xor_sync(0xffffffffu, q, o);
    }
    if (lane == 0) { g_p[w] = p; g_q[w] = q; }
}

__global__ void k_rel_dots(const float* __restrict__ rel, int NR) {
    int w = (blockIdx.x * blockDim.x + threadIdx.x) >> 5;
    int lane = threadIdx.x & 31;
    if (w >= NR) return;
    float4 v  = ((const float4*)(rel + (size_t)w * DD))[lane];
    float4 wa = ((const float4*)(g_wa + 128))[lane];
    float s = v.x*wa.x + v.y*wa.y + v.z*wa.z + v.w*wa.w;
    #pragma unroll
    for (int o = 16; o; o >>= 1) s += __shfl_xor_sync(0xffffffffu, s, o);
    if (lane == 0) g_s[w] = s;
}

// relW2[r][u] = rel[r] . W2[:,u]  (W rows 128..255)
__global__ void k_relW2(const float* __restrict__ rel, const float* __restrict__ W, int NR) {
    int rn = blockIdx.x;
    if (rn >= NR) return;
    int u = threadIdx.x;
    const float* rrow = rel + (size_t)rn * DD;
    float s = 0.f;
    #pragma unroll 8
    for (int k = 0; k < DD; k++) s = fmaf(rrow[k], W[(size_t)(128 + k) * DD + u], s);
    g_relW2[rn * DD + u] = s;
}

// ---------- counting sort of edges by h ----------
__global__ void k_hist(const int* __restrict__ h, int E) {
    int e = blockIdx.x * blockDim.x + threadIdx.x;
    if (e < E) atomicAdd(&g_cnt[h[e]], 1);
}

// per-chunk exclusive scan (chunk = SCHUNK, 256 threads x 8 elems)
__global__ void k_scan1(int NE) {
    __shared__ int sp[256];
    int b = blockIdx.x, tid = threadIdx.x;
    int base = b * SCHUNK + tid * 8;
    int v[8], s = 0;
    #pragma unroll
    for (int i = 0; i < 8; i++) {
        int idx = base + i;
        v[i] = s;
        s += (idx < NE) ? g_cnt[idx] : 0;
    }
    sp[tid] = s;
    __syncthreads();
    #pragma unroll
    for (int o = 1; o < 256; o <<= 1) {
        int x = 0;
        if (tid >= o) x = sp[tid - o];
        __syncthreads();
        if (tid >= o) sp[tid] += x;
        __syncthreads();
    }
    int excl = (tid == 0) ? 0 : sp[tid - 1];
    #pragma unroll
    for (int i = 0; i < 8; i++) {
        int idx = base + i;
        if (idx < NE) g_off[idx] = v[i] + excl;
    }
    if (tid == 0) g_blk[b] = sp[255];
}

__global__ void k_scan2(int nblk) {
    if (threadIdx.x == 0) {
        int run = 0;
        for (int b = 0; b < nblk; b++) {
            g_blkoff[b] = run;
            run += g_blk[b];
        }
    }
}

__global__ void k_scan3(int NE) {
    int i = blockIdx.x * blockDim.x + threadIdx.x;
    if (i < NE) {
        int o = g_off[i] + g_blkoff[i / SCHUNK];
        g_off[i] = o;
        g_cur[i] = o;
    }
}

__global__ void k_bucket(const int* __restrict__ h, int E) {
    int e = blockIdx.x * blockDim.x + threadIdx.x;
    if (e < E) {
        int pos = atomicAdd(&g_cur[h[e]], 1);
        g_eidx[pos] = e;
    }
}

// ---------- tf32 tensor-core GEMM: [acc | embW3] = emb @ [W1 | W3] ----------
__global__ __launch_bounds__(256) void k_mm(const float* __restrict__ emb,
                                            const float* __restrict__ W, int NE) {
    __shared__ uint32_t As[64 * 36];
    __shared__ uint32_t Bs[32 * 264];
    int tid  = threadIdx.x;
    int lane = tid & 31;
    int wid  = tid >> 5;
    int g  = lane >> 2;
    int t4 = lane & 3;
    int wm = wid >> 2;
    int wn = wid & 3;
    int n0 = blockIdx.x * 64;

    float c[2][8][4];
    #pragma unroll
    for (int i = 0; i < 2; i++)
        #pragma unroll
        for (int j = 0; j < 8; j++)
            #pragma unroll
            for (int k = 0; k < 4; k++) c[i][j][k] = 0.f;

    #pragma unroll 1
    for (int kc = 0; kc < 4; kc++) {
        int k0 = kc * 32;
        #pragma unroll
        for (int i = 0; i < 2; i++) {
            int idx = tid + i * 256;
            int row = idx >> 3;
            int q   = idx & 7;
            int n = n0 + row;
            float4 v = make_float4(0.f, 0.f, 0.f, 0.f);
            if (n < NE) v = *(const float4*)(emb + (size_t)n * DD + k0 + q * 4);
            *(uint4*)&As[row * 36 + q * 4] =
                make_uint4(f2tf(v.x), f2tf(v.y), f2tf(v.z), f2tf(v.w));
        }
        #pragma unroll
        for (int i = 0; i < 8; i++) {
            int idx = tid + i * 256;
            int k  = idx >> 6;
            int u  = (idx & 63) * 4;
            const float* src = (u < 128)
                ? (W + (size_t)(k0 + k) * DD + u)
                : (W + (size_t)(256 + k0 + k) * DD + (u - 128));
            float4 v = *(const float4*)src;
            *(uint4*)&Bs[k * 264 + u] =
                make_uint4(f2tf(v.x), f2tf(v.y), f2tf(v.z), f2tf(v.w));
        }
        __syncthreads();
        #pragma unroll
        for (int ks = 0; ks < 4; ks++) {
            int kk = ks * 8;
            uint32_t a[2][4], b[8][2];
            #pragma unroll
            for (int fm = 0; fm < 2; fm++) {
                int mr = wm * 32 + fm * 16 + g;
                a[fm][0] = As[mr * 36 + kk + t4];
                a[fm][1] = As[(mr + 8) * 36 + kk + t4];
                a[fm][2] = As[mr * 36 + kk + t4 + 4];
                a[fm][3] = As[(mr + 8) * 36 + kk + t4 + 4];
            }
            #pragma unroll
            for (int fn = 0; fn < 8; fn++) {
                int col = wn * 64 + fn * 8 + g;
                b[fn][0] = Bs[(kk + t4) * 264 + col];
                b[fn][1] = Bs[(kk + t4 + 4) * 264 + col];
            }
            #pragma unroll
            for (int fm = 0; fm < 2; fm++)
                #pragma unroll
                for (int fn = 0; fn < 8; fn++)
                    asm volatile(
                        "mma.sync.aligned.m16n8k8.row.col.f32.tf32.tf32.f32 "
                        "{%0,%1,%2,%3}, {%4,%5,%6,%7}, {%8,%9}, {%0,%1,%2,%3};"
                        : "+f"(c[fm][fn][0]), "+f"(c[fm][fn][1]),
                          "+f"(c[fm][fn][2]), "+f"(c[fm][fn][3])
                        : "r"(a[fm][0]), "r"(a[fm][1]), "r"(a[fm][2]), "r"(a[fm][3]),
                          "r"(b[fn][0]), "r"(b[fn][1]));
        }
        __syncthreads();
    }

    float* dstbase = (wn < 2) ? g_acc : g_embW3;
    int colbase = (wn < 2) ? wn * 64 : (wn - 2) * 64;
    #pragma unroll
    for (int fm = 0; fm < 2; fm++) {
        #pragma unroll
        for (int fn = 0; fn < 8; fn++) {
            int col = colbase + fn * 8 + t4 * 2;
            int r0 = n0 + wm * 32 + fm * 16 + g;
            if (r0 < NE)
                *(float2*)&dstbase[(size_t)r0 * DD + col] =
                    make_float2(c[fm][fn][0], c[fm][fn][1]);
            int r1 = r0 + 8;
            if (r1 < NE)
                *(float2*)&dstbase[(size_t)r1 * DD + col] =
                    make_float2(c[fm][fn][2], c[fm][fn][3]);
        }
    }
}

// ---------- fused per-segment kernel: scores, softmax, weighted sum, output ----------
__global__ __launch_bounds__(256) void k_seg(const int* __restrict__ r,
                                             const int* __restrict__ t,
                                             const float* __restrict__ ab,
                                             const float* __restrict__ bias,
                                             float* __restrict__ out, int NE) {
    int n = blockIdx.x * 8 + (threadIdx.x >> 5);
    int lane = threadIdx.x & 31;
    if (n >= NE) return;
    float4 b4 = ((const float4*)bias)[lane];
    float4* outp = ((float4*)out) + (size_t)n * 32 + lane;
    int deg = g_cnt[n];
    if (deg == 0) {
        float4 o;
        o.x = fmaxf(b4.x, 0.f); o.y = fmaxf(b4.y, 0.f);
        o.z = fmaxf(b4.z, 0.f); o.w = fmaxf(b4.w, 0.f);
        *outp = o;
        return;
    }
    int off = g_off[n];
    float pn = g_p[n] + ab[0];

    // pass A: scores + max
    float mx = -INFINITY;
    for (int i = lane; i < deg; i += 32) {
        int e = g_eidx[off + i];
        float x = pn + g_s[r[e]] + g_q[t[e]];
        float sc = x >= 0.f ? x : 0.04f * x;
        g_score[off + i] = sc;
        mx = fmaxf(mx, sc);
    }
    #pragma unroll
    for (int o = 16; o; o >>= 1) mx = fmaxf(mx, __shfl_xor_sync(0xffffffffu, mx, o));

    // pass B: exp + denom
    float ds = 0.f;
    for (int i = lane; i < deg; i += 32) {
        float ex = expf(g_score[off + i] - mx);
        g_score[off + i] = ex;
        ds += ex;
    }
    #pragma unroll
    for (int o = 16; o; o >>= 1) ds += __shfl_xor_sync(0xffffffffu, ds, o);
    float inv = 1.f / ds;

    // pass C: edge-serial weighted accumulation over feature dims
    float4 acc = ((const float4*)g_acc)[(size_t)n * 32 + lane];
    for (int i = 0; i < deg; i++) {
        int e = g_eidx[off + i];
        float alpha = g_score[off + i] * inv;
        float4 rv = ((const float4*)g_relW2)[r[e] * 32 + lane];
        float4 tv = ((const float4*)g_embW3)[(size_t)t[e] * 32 + lane];
        acc.x = fmaf(alpha, rv.x + tv.x, acc.x);
        acc.y = fmaf(alpha, rv.y + tv.y, acc.y);
        acc.z = fmaf(alpha, rv.z + tv.z, acc.z);
        acc.w = fmaf(alpha, rv.w + tv.w, acc.w);
    }
    float4 o;
    o.x = fmaxf(acc.x + b4.x, 0.f);
    o.y = fmaxf(acc.y + b4.y, 0.f);
    o.z = fmaxf(acc.z + b4.z, 0.f);
    o.w = fmaxf(acc.w + b4.w, 0.f);
    *outp = o;
}

extern "C" void kernel_launch(void* const* d_in, const int* in_sizes, int n_in,
                              void* d_out, int out_size) {
    const int*   h    = (const int*)d_in[0];
    const int*   r    = (const int*)d_in[1];
    const int*   t    = (const int*)d_in[2];
    const float* emb  = (const float*)d_in[3];
    const float* rel  = (const float*)d_in[4];
    const float* W    = (const float*)d_in[5];
    const float* a    = (const float*)d_in[6];
    const float* ab   = (const float*)d_in[7];
    const float* bias = (const float*)d_in[8];
    float* out = (float*)d_out;

    int E  = in_sizes[0];
    int NE = in_sizes[3] / DD;
    int NR = in_sizes[4] / DD;
    int nblk = (NE + SCHUNK - 1) / SCHUNK;

    k_wa<<<2, 256>>>(W, a);
    k_zero_cnt<<<(NE + 255) / 256, 256>>>(NE);
    k_hist<<<(E + 255) / 256, 256>>>(h, E);
    k_scan1<<<nblk, 256>>>(NE);
    k_scan2<<<1, 32>>>(nblk);
    k_scan3<<<(NE + 255) / 256, 256>>>(NE);
    k_bucket<<<(E + 255) / 256, 256>>>(h, E);
    k_entity_dots<<<(NE * 32 + 255) / 256, 256>>>(emb, NE);
    k_rel_dots<<<(NR * 32 + 255) / 256, 256>>>(rel, NR);
    k_relW2<<<NR, 128>>>(rel, W, NR);
    k_mm<<<(NE + 63) / 64, 256>>>(emb, W, NE);
    k_seg<<<(NE + 7) / 8, 256>>>(r, t, ab, bias, out, NE);
}

// round 6
// speedup vs baseline: 1.1268x; 1.1268x over previous
#include <cuda_runtime.h>
#include <math.h>
#include <stdint.h>

// Problem constants (fixed by setup_inputs)
#define EMAX 500000
#define NEMAX 100000
#define NRMAX 1008
#define DD 128
#define KTOT 384

// ---------- device scratch (static; no allocation allowed) ----------
__device__ __align__(16) float g_wa[KTOT];          // W @ a
__device__ float g_p[NEMAX];                        // emb[n] . wa[0:128]
__device__ float g_q[NEMAX];                        // emb[n] . wa[256:384]
__device__ float g_s[NRMAX];                        // rel[r] . wa[128:256]
__device__ float g_score[EMAX];                     // exp(score) per edge
__device__ float g_denom[NEMAX];                    // segment sum of exp
__device__ __align__(16) float g_acc[NEMAX * DD];   // emb@W1, then += scatter
__device__ __align__(16) float g_embW3[NEMAX * DD]; // emb@W3
__device__ __align__(16) float g_relW2[NRMAX * DD]; // rel@W2

// ---------- helpers ----------
__device__ __forceinline__ uint32_t f2tf(float f) {
    uint32_t r;
    asm("cvt.rna.tf32.f32 %0, %1;" : "=r"(r) : "f"(f));
    return r;
}

// ---------- small kernels ----------
__global__ void k_wa(const float* __restrict__ W, const float* __restrict__ a) {
    int k = blockIdx.x * blockDim.x + threadIdx.x;
    if (k < KTOT) {
        const float* row = W + (size_t)k * DD;
        float s = 0.f;
        #pragma unroll 8
        for (int u = 0; u < DD; u++) s = fmaf(row[u], a[u], s);
        g_wa[k] = s;
    }
}

__global__ void k_init(int NE) {
    int i = blockIdx.x * blockDim.x + threadIdx.x;
    if (i < NE) g_denom[i] = 0.f;
}

__global__ void k_entity_dots(const float* __restrict__ emb, int NE) {
    int w = (blockIdx.x * blockDim.x + threadIdx.x) >> 5;
    int lane = threadIdx.x & 31;
    if (w >= NE) return;
    float4 v   = ((const float4*)(emb + (size_t)w * DD))[lane];
    float4 wa0 = ((const float4*)g_wa)[lane];
    float4 wa2 = ((const float4*)(g_wa + 256))[lane];
    float p = v.x*wa0.x + v.y*wa0.y + v.z*wa0.z + v.w*wa0.w;
    float q = v.x*wa2.x + v.y*wa2.y + v.z*wa2.z + v.w*wa2.w;
    #pragma unroll
    for (int o = 16; o; o >>= 1) {
        p += __shfl_xor_sync(0xffffffffu, p, o);
        q += __shfl_xor_sync(0xffffffffu, q, o);
    }
    if (lane == 0) { g_p[w] = p; g_q[w] = q; }
}

__global__ void k_rel_dots(const float* __restrict__ rel, int NR) {
    int w = (blockIdx.x * blockDim.x + threadIdx.x) >> 5;
    int lane = threadIdx.x & 31;
    if (w >= NR) return;
    float4 v  = ((const float4*)(rel + (size_t)w * DD))[lane];
    float4 wa = ((const float4*)(g_wa + 128))[lane];
    float s = v.x*wa.x + v.y*wa.y + v.z*wa.z + v.w*wa.w;
    #pragma unroll
    for (int o = 16; o; o >>= 1) s += __shfl_xor_sync(0xffffffffu, s, o);
    if (lane == 0) g_s[w] = s;
}

// single fused score pass: score -> exp -> denom accumulation (no max pass;
// exp(score)/sum(exp(score)) is identical to max-shifted softmax and scores
// are O(6) here, so no overflow)
__global__ void k_score(const int* __restrict__ h, const int* __restrict__ r,
                        const int* __restrict__ t, const float* __restrict__ ab, int E) {
    int e = blockIdx.x * blockDim.x + threadIdx.x;
    if (e >= E) return;
    int hn = h[e];
    float x = g_p[hn] + g_s[r[e]] + g_q[t[e]] + ab[0];
    // leaky(leaky(x)) with alpha=0.2: x>=0 -> x ; x<0 -> 0.04x
    float sc = x >= 0.f ? x : 0.04f * x;
    float ex = expf(sc);
    g_score[e] = ex;
    atomicAdd(&g_denom[hn], ex);
}

// relW2[r][u] = rel[r] . W2[:,u]  (W rows 128..255)
__global__ void k_relW2(const float* __restrict__ rel, const float* __restrict__ W, int NR) {
    int rn = blockIdx.x;
    if (rn >= NR) return;
    int u = threadIdx.x;
    const float* rrow = rel + (size_t)rn * DD;
    float s = 0.f;
    #pragma unroll 8
    for (int k = 0; k < DD; k++) s = fmaf(rrow[k], W[(size_t)(128 + k) * DD + u], s);
    g_relW2[rn * DD + u] = s;
}

// ---------- tf32 tensor-core GEMM: [acc | embW3] = emb @ [W1 | W3] ----------
__global__ __launch_bounds__(256) void k_mm(const float* __restrict__ emb,
                                            const float* __restrict__ W, int NE) {
    __shared__ uint32_t As[64 * 36];
    __shared__ uint32_t Bs[32 * 264];
    int tid  = threadIdx.x;
    int lane = tid & 31;
    int wid  = tid >> 5;
    int g  = lane >> 2;
    int t4 = lane & 3;
    int wm = wid >> 2;
    int wn = wid & 3;
    int n0 = blockIdx.x * 64;

    float c[2][8][4];
    #pragma unroll
    for (int i = 0; i < 2; i++)
        #pragma unroll
        for (int j = 0; j < 8; j++)
            #pragma unroll
            for (int k = 0; k < 4; k++) c[i][j][k] = 0.f;

    #pragma unroll 1
    for (int kc = 0; kc < 4; kc++) {
        int k0 = kc * 32;
        #pragma unroll
        for (int i = 0; i < 2; i++) {
            int idx = tid + i * 256;
            int row = idx >> 3;
            int q   = idx & 7;
            int n = n0 + row;
            float4 v = make_float4(0.f, 0.f, 0.f, 0.f);
            if (n < NE) v = *(const float4*)(emb + (size_t)n * DD + k0 + q * 4);
            *(uint4*)&As[row * 36 + q * 4] =
                make_uint4(f2tf(v.x), f2tf(v.y), f2tf(v.z), f2tf(v.w));
        }
        #pragma unroll
        for (int i = 0; i < 8; i++) {
            int idx = tid + i * 256;
            int k  = idx >> 6;
            int u  = (idx & 63) * 4;
            const float* src = (u < 128)
                ? (W + (size_t)(k0 + k) * DD + u)
                : (W + (size_t)(256 + k0 + k) * DD + (u - 128));
            float4 v = *(const float4*)src;
            *(uint4*)&Bs[k * 264 + u] =
                make_uint4(f2tf(v.x), f2tf(v.y), f2tf(v.z), f2tf(v.w));
        }
        __syncthreads();
        #pragma unroll
        for (int ks = 0; ks < 4; ks++) {
            int kk = ks * 8;
            uint32_t a[2][4], b[8][2];
            #pragma unroll
            for (int fm = 0; fm < 2; fm++) {
                int mr = wm * 32 + fm * 16 + g;
                a[fm][0] = As[mr * 36 + kk + t4];
                a[fm][1] = As[(mr + 8) * 36 + kk + t4];
                a[fm][2] = As[mr * 36 + kk + t4 + 4];
                a[fm][3] = As[(mr + 8) * 36 + kk + t4 + 4];
            }
            #pragma unroll
            for (int fn = 0; fn < 8; fn++) {
                int col = wn * 64 + fn * 8 + g;
                b[fn][0] = Bs[(kk + t4) * 264 + col];
                b[fn][1] = Bs[(kk + t4 + 4) * 264 + col];
            }
            #pragma unroll
            for (int fm = 0; fm < 2; fm++)
                #pragma unroll
                for (int fn = 0; fn < 8; fn++)
                    asm volatile(
                        "mma.sync.aligned.m16n8k8.row.col.f32.tf32.tf32.f32 "
                        "{%0,%1,%2,%3}, {%4,%5,%6,%7}, {%8,%9}, {%0,%1,%2,%3};"
                        : "+f"(c[fm][fn][0]), "+f"(c[fm][fn][1]),
                          "+f"(c[fm][fn][2]), "+f"(c[fm][fn][3])
                        : "r"(a[fm][0]), "r"(a[fm][1]), "r"(a[fm][2]), "r"(a[fm][3]),
                          "r"(b[fn][0]), "r"(b[fn][1]));
        }
        __syncthreads();
    }

    float* dstbase = (wn < 2) ? g_acc : g_embW3;
    int colbase = (wn < 2) ? wn * 64 : (wn - 2) * 64;
    #pragma unroll
    for (int fm = 0; fm < 2; fm++) {
        #pragma unroll
        for (int fn = 0; fn < 8; fn++) {
            int col = colbase + fn * 8 + t4 * 2;
            int r0 = n0 + wm * 32 + fm * 16 + g;
            if (r0 < NE)
                *(float2*)&dstbase[(size_t)r0 * DD + col] =
                    make_float2(c[fm][fn][0], c[fm][fn][1]);
            int r1 = r0 + 8;
            if (r1 < NE)
                *(float2*)&dstbase[(size_t)r1 * DD + col] =
                    make_float2(c[fm][fn][2], c[fm][fn][3]);
        }
    }
}

// one warp per edge: acc[h] += alpha * (relW2[r] + embW3[t])
// all loads issued before the RED for max MLP
__global__ __launch_bounds__(256) void k_scatter(const int* __restrict__ h,
                                                 const int* __restrict__ r,
                                                 const int* __restrict__ t, int E) {
    int e = (blockIdx.x * blockDim.x + threadIdx.x) >> 5;
    int lane = threadIdx.x & 31;
    if (e >= E) return;
    int hn = h[e], rn = r[e], tn = t[e];
    float sc = g_score[e];
    float dn = g_denom[hn];
    float4 rv = ((const float4*)g_relW2)[rn * 32 + lane];
    float4 tv = ((const float4*)g_embW3)[(size_t)tn * 32 + lane];
    float alpha = sc / dn;
    float4* dst = ((float4*)g_acc) + (size_t)hn * 32 + lane;
    atomicAdd(dst, make_float4(alpha * (rv.x + tv.x), alpha * (rv.y + tv.y),
                               alpha * (rv.z + tv.z), alpha * (rv.w + tv.w)));
}

// out[n] = relu(mask(n) * acc[n] + bias)
__global__ void k_out(const float* __restrict__ bias, float* __restrict__ out, int NE) {
    int idx = blockIdx.x * blockDim.x + threadIdx.x;
    if (idx >= NE * 32) return;
    int n = idx >> 5, u4 = idx & 31;
    float m = g_denom[n] > 0.f ? 1.f : 0.f;
    float4 a = ((const float4*)g_acc)[idx];
    float4 b = ((const float4*)bias)[u4];
    float4 o;
    o.x = fmaxf(fmaf(a.x, m, b.x), 0.f);
    o.y = fmaxf(fmaf(a.y, m, b.y), 0.f);
    o.z = fmaxf(fmaf(a.z, m, b.z), 0.f);
    o.w = fmaxf(fmaf(a.w, m, b.w), 0.f);
    ((float4*)out)[idx] = o;
}

extern "C" void kernel_launch(void* const* d_in, const int* in_sizes, int n_in,
                              void* d_out, int out_size) {
    const int*   h    = (const int*)d_in[0];
    const int*   r    = (const int*)d_in[1];
    const int*   t    = (const int*)d_in[2];
    const float* emb  = (const float*)d_in[3];
    const float* rel  = (const float*)d_in[4];
    const float* W    = (const float*)d_in[5];
    const float* a    = (const float*)d_in[6];
    const float* ab   = (const float*)d_in[7];
    const float* bias = (const float*)d_in[8];
    float* out = (float*)d_out;

    int E  = in_sizes[0];
    int NE = in_sizes[3] / DD;
    int NR = in_sizes[4] / DD;

    k_wa<<<2, 256>>>(W, a);
    k_init<<<(NE + 255) / 256, 256>>>(NE);
    k_entity_dots<<<(NE * 32 + 255) / 256, 256>>>(emb, NE);
    k_rel_dots<<<(NR * 32 + 255) / 256, 256>>>(rel, NR);
    k_mm<<<(NE + 63) / 64, 256>>>(emb, W, NE);
    k_relW2<<<NR, 128>>>(rel, W, NR);
    k_score<<<(E + 255) / 256, 256>>>(h, r, t, ab, E);
    k_scatter<<<(E * 32 + 255) / 256, 256>>>(h, r, t, E);
    k_out<<<(NE * 32 + 255) / 256, 256>>>(bias, out, NE);
}

// round 8
// speedup vs baseline: 1.2423x; 1.1025x over previous
#include <cuda_runtime.h>
#include <cuda_fp16.h>
#include <math.h>
#include <stdint.h>

// Problem constants (fixed by setup_inputs)
#define EMAX 500000
#define NEMAX 100000
#define NRMAX 1008
#define DD 128
#define KTOT 384

// ---------- device scratch (static; no allocation allowed) ----------
__device__ __align__(16) float g_wa[KTOT];          // W @ a
__device__ float g_p[NEMAX];                        // emb[n] . wa[0:128]
__device__ float g_q[NEMAX];                        // emb[n] . wa[256:384]
__device__ float g_s[NRMAX];                        // rel[r] . wa[128:256]
__device__ float g_score[EMAX];                     // exp(score) per edge
__device__ float g_denom[NEMAX];                    // segment sum of exp
__device__ __align__(16) float g_acc[NEMAX * DD];   // emb@W1, then += scatter
__device__ __align__(16) __half g_embW3h[NEMAX * DD]; // emb@W3 (fp16)
__device__ __align__(16) __half g_relW2h[NRMAX * DD]; // rel@W2 (fp16)

// ---------- helpers ----------
__device__ __forceinline__ uint32_t f2tf(float f) {
    uint32_t r;
    asm("cvt.rna.tf32.f32 %0, %1;" : "=r"(r) : "f"(f));
    return r;
}

// ---------- small kernels ----------
__global__ void k_wa(const float* __restrict__ W, const float* __restrict__ a) {
    int k = blockIdx.x * blockDim.x + threadIdx.x;
    if (k < KTOT) {
        const float* row = W + (size_t)k * DD;
        float s = 0.f;
        #pragma unroll 8
        for (int u = 0; u < DD; u++) s = fmaf(row[u], a[u], s);
        g_wa[k] = s;
    }
}

__global__ void k_init(int NE) {
    int i = blockIdx.x * blockDim.x + threadIdx.x;
    if (i < NE) g_denom[i] = 0.f;
}

__global__ void k_entity_dots(const float* __restrict__ emb, int NE) {
    int w = (blockIdx.x * blockDim.x + threadIdx.x) >> 5;
    int lane = threadIdx.x & 31;
    if (w >= NE) return;
    float4 v   = ((const float4*)(emb + (size_t)w * DD))[lane];
    float4 wa0 = ((const float4*)g_wa)[lane];
    float4 wa2 = ((const float4*)(g_wa + 256))[lane];
    float p = v.x*wa0.x + v.y*wa0.y + v.z*wa0.z + v.w*wa0.w;
    float q = v.x*wa2.x + v.y*wa2.y + v.z*wa2.z + v.w*wa2.w;
    #pragma unroll
    for (int o = 16; o; o >>= 1) {
        p += __shfl_xor_sync(0xffffffffu, p, o);
        q += __shfl_xor_sync(0xffffffffu, q, o);
    }
    if (lane == 0) { g_p[w] = p; g_q[w] = q; }
}

__global__ void k_rel_dots(const float* __restrict__ rel, int NR) {
    int w = (blockIdx.x * blockDim.x + threadIdx.x) >> 5;
    int lane = threadIdx.x & 31;
    if (w >= NR) return;
    float4 v  = ((const float4*)(rel + (size_t)w * DD))[lane];
    float4 wa = ((const float4*)(g_wa + 128))[lane];
    float s = v.x*wa.x + v.y*wa.y + v.z*wa.z + v.w*wa.w;
    #pragma unroll
    for (int o = 16; o; o >>= 1) s += __shfl_xor_sync(0xffffffffu, s, o);
    if (lane == 0) g_s[w] = s;
}

// single fused score pass: score -> exp -> denom accumulation (no max pass;
// exp(score)/sum(exp(score)) is identical to max-shifted softmax and scores
// are O(6) here, so no overflow)
__global__ void k_score(const int* __restrict__ h, const int* __restrict__ r,
                        const int* __restrict__ t, const float* __restrict__ ab, int E) {
    int e = blockIdx.x * blockDim.x + threadIdx.x;
    if (e >= E) return;
    int hn = h[e];
    float x = g_p[hn] + g_s[r[e]] + g_q[t[e]] + ab[0];
    float sc = x >= 0.f ? x : 0.04f * x;
    float ex = expf(sc);
    g_score[e] = ex;
    atomicAdd(&g_denom[hn], ex);
}

// relW2[r][u] = rel[r] . W2[:,u]  (W rows 128..255), stored fp16
__global__ void k_relW2(const float* __restrict__ rel, const float* __restrict__ W, int NR) {
    int rn = blockIdx.x;
    if (rn >= NR) return;
    int u = threadIdx.x;
    const float* rrow = rel + (size_t)rn * DD;
    float s = 0.f;
    #pragma unroll 8
    for (int k = 0; k < DD; k++) s = fmaf(rrow[k], W[(size_t)(128 + k) * DD + u], s);
    g_relW2h[rn * DD + u] = __float2half_rn(s);
}

// ---------- tf32 tensor-core GEMM: [acc(f32) | embW3(f16)] = emb @ [W1 | W3] ----------
__global__ __launch_bounds__(256) void k_mm(const float* __restrict__ emb,
                                            const float* __restrict__ W, int NE) {
    __shared__ uint32_t As[64 * 36];
    __shared__ uint32_t Bs[32 * 264];
    int tid  = threadIdx.x;
    int lane = tid & 31;
    int wid  = tid >> 5;
    int g  = lane >> 2;
    int t4 = lane & 3;
    int wm = wid >> 2;
    int wn = wid & 3;
    int n0 = blockIdx.x * 64;

    float c[2][8][4];
    #pragma unroll
    for (int i = 0; i < 2; i++)
        #pragma unroll
        for (int j = 0; j < 8; j++)
            #pragma unroll
            for (int k = 0; k < 4; k++) c[i][j][k] = 0.f;

    #pragma unroll 1
    for (int kc = 0; kc < 4; kc++) {
        int k0 = kc * 32;
        #pragma unroll
        for (int i = 0; i < 2; i++) {
            int idx = tid + i * 256;
            int row = idx >> 3;
            int q   = idx & 7;
            int n = n0 + row;
            float4 v = make_float4(0.f, 0.f, 0.f, 0.f);
            if (n < NE) v = *(const float4*)(emb + (size_t)n * DD + k0 + q * 4);
            *(uint4*)&As[row * 36 + q * 4] =
                make_uint4(f2tf(v.x), f2tf(v.y), f2tf(v.z), f2tf(v.w));
        }
        #pragma unroll
        for (int i = 0; i < 8; i++) {
            int idx = tid + i * 256;
            int k  = idx >> 6;
            int u  = (idx & 63) * 4;
            const float* src = (u < 128)
                ? (W + (size_t)(k0 + k) * DD + u)
                : (W + (size_t)(256 + k0 + k) * DD + (u - 128));
            float4 v = *(const float4*)src;
            *(uint4*)&Bs[k * 264 + u] =
                make_uint4(f2tf(v.x), f2tf(v.y), f2tf(v.z), f2tf(v.w));
        }
        __syncthreads();
        #pragma unroll
        for (int ks = 0; ks < 4; ks++) {
            int kk = ks * 8;
            uint32_t a[2][4], b[8][2];
            #pragma unroll
            for (int fm = 0; fm < 2; fm++) {
                int mr = wm * 32 + fm * 16 + g;
                a[fm][0] = As[mr * 36 + kk + t4];
                a[fm][1] = As[(mr + 8) * 36 + kk + t4];
                a[fm][2] = As[mr * 36 + kk + t4 + 4];
                a[fm][3] = As[(mr + 8) * 36 + kk + t4 + 4];
            }
            #pragma unroll
            for (int fn = 0; fn < 8; fn++) {
                int col = wn * 64 + fn * 8 + g;
                b[fn][0] = Bs[(kk + t4) * 264 + col];
                b[fn][1] = Bs[(kk + t4 + 4) * 264 + col];
            }
            #pragma unroll
            for (int fm = 0; fm < 2; fm++)
                #pragma unroll
                for (int fn = 0; fn < 8; fn++)
                    asm volatile(
                        "mma.sync.aligned.m16n8k8.row.col.f32.tf32.tf32.f32 "
                        "{%0,%1,%2,%3}, {%4,%5,%6,%7}, {%8,%9}, {%0,%1,%2,%3};"
                        : "+f"(c[fm][fn][0]), "+f"(c[fm][fn][1]),
                          "+f"(c[fm][fn][2]), "+f"(c[fm][fn][3])
                        : "r"(a[fm][0]), "r"(a[fm][1]), "r"(a[fm][2]), "r"(a[fm][3]),
                          "r"(b[fn][0]), "r"(b[fn][1]));
        }
        __syncthreads();
    }

    if (wn < 2) {
        // cols 0-127 of C -> g_acc fp32
        int colbase = wn * 64;
        #pragma unroll
        for (int fm = 0; fm < 2; fm++) {
            #pragma unroll
            for (int fn = 0; fn < 8; fn++) {
                int col = colbase + fn * 8 + t4 * 2;
                int r0 = n0 + wm * 32 + fm * 16 + g;
                if (r0 < NE)
                    *(float2*)&g_acc[(size_t)r0 * DD + col] =
                        make_float2(c[fm][fn][0], c[fm][fn][1]);
                int r1 = r0 + 8;
                if (r1 < NE)
                    *(float2*)&g_acc[(size_t)r1 * DD + col] =
                        make_float2(c[fm][fn][2], c[fm][fn][3]);
            }
        }
    } else {
        // cols 128-255 of C -> g_embW3h fp16
        int colbase = (wn - 2) * 64;
        #pragma unroll
        for (int fm = 0; fm < 2; fm++) {
            #pragma unroll
            for (int fn = 0; fn < 8; fn++) {
                int col = colbase + fn * 8 + t4 * 2;
                int r0 = n0 + wm * 32 + fm * 16 + g;
                if (r0 < NE)
                    *(__half2*)&g_embW3h[(size_t)r0 * DD + col] =
                        __floats2half2_rn(c[fm][fn][0], c[fm][fn][1]);
                int r1 = r0 + 8;
                if (r1 < NE)
                    *(__half2*)&g_embW3h[(size_t)r1 * DD + col] =
                        __floats2half2_rn(c[fm][fn][2], c[fm][fn][3]);
            }
        }
    }
}

// one warp per edge: acc[h] += alpha * (relW2[r] + embW3[t]); fp16 gathers, fp32 RED
__global__ __launch_bounds__(256) void k_scatter(const int* __restrict__ h,
                                                 const int* __restrict__ r,
                                                 const int* __restrict__ t, int E) {
    int e = (blockIdx.x * blockDim.x + threadIdx.x) >> 5;
    int lane = threadIdx.x & 31;
    if (e >= E) return;
    int hn = h[e], rn = r[e], tn = t[e];
    float sc = g_score[e];
    float dn = g_denom[hn];
    // 4 halves per lane from each table (8 bytes, coalesced 256B/row)
    const __half2* rp = (const __half2*)(g_relW2h + (size_t)rn * DD) + lane * 2;
    const __half2* tp = (const __half2*)(g_embW3h + (size_t)tn * DD) + lane * 2;
    __half2 r0 = rp[0], r1 = rp[1];
    __half2 t0 = tp[0], t1 = tp[1];
    float alpha = sc / dn;
    float2 fr0 = __half22float2(r0), fr1 = __half22float2(r1);
    float2 ft0 = __half22float2(t0), ft1 = __half22float2(t1);
    float4* dst = ((float4*)g_acc) + (size_t)hn * 32 + lane;
    atomicAdd(dst, make_float4(alpha * (fr0.x + ft0.x), alpha * (fr0.y + ft0.y),
                               alpha * (fr1.x + ft1.x), alpha * (fr1.y + ft1.y)));
}

// out[n] = relu(mask(n) * acc[n] + bias)
__global__ void k_out(const float* __restrict__ bias, float* __restrict__ out, int NE) {
    int idx = blockIdx.x * blockDim.x + threadIdx.x;
    if (idx >= NE * 32) return;
    int n = idx >> 5, u4 = idx & 31;
    float m = g_denom[n] > 0.f ? 1.f : 0.f;
    float4 a = ((const float4*)g_acc)[idx];
    float4 b = ((const float4*)bias)[u4];
    float4 o;
    o.x = fmaxf(fmaf(a.x, m, b.x), 0.f);
    o.y = fmaxf(fmaf(a.y, m, b.y), 0.f);
    o.z = fmaxf(fmaf(a.z, m, b.z), 0.f);
    o.w = fmaxf(fmaf(a.w, m, b.w), 0.f);
    ((float4*)out)[idx] = o;
}

extern "C" void kernel_launch(void* const* d_in, const int* in_sizes, int n_in,
                              void* d_out, int out_size) {
    const int*   h    = (const int*)d_in[0];
    const int*   r    = (const int*)d_in[1];
    const int*   t    = (const int*)d_in[2];
    const float* emb  = (const float*)d_in[3];
    const float* rel  = (const float*)d_in[4];
    const float* W    = (const float*)d_in[5];
    const float* a    = (const float*)d_in[6];
    const float* ab   = (const float*)d_in[7];
    const float* bias = (const float*)d_in[8];
    float* out = (float*)d_out;

    int E  = in_sizes[0];
    int NE = in_sizes[3] / DD;
    int NR = in_sizes[4] / DD;

    k_wa<<<2, 256>>>(W, a);
    k_init<<<(NE + 255) / 256, 256>>>(NE);
    k_entity_dots<<<(NE * 32 + 255) / 256, 256>>>(emb, NE);
    k_rel_dots<<<(NR * 32 + 255) / 256, 256>>>(rel, NR);
    k_mm<<<(NE + 63) / 64, 256>>>(emb, W, NE);
    k_relW2<<<NR, 128>>>(rel, W, NR);
    k_score<<<(E + 255) / 256, 256>>>(h, r, t, ab, E);
    k_scatter<<<(E * 32 + 255) / 256, 256>>>(h, r, t, E);
    k_out<<<(NE * 32 + 255) / 256, 256>>>(bias, out, NE);
}

// round 9
// speedup vs baseline: 1.2572x; 1.0121x over previous
#include <cuda_runtime.h>
#include <cuda_fp16.h>
#include <math.h>
#include <stdint.h>

// Problem constants (fixed by setup_inputs)
#define EMAX 500000
#define NEMAX 100000
#define NRMAX 1008
#define DD 128
#define KTOT 384

// ---------- device scratch (static; no allocation allowed) ----------
__device__ __align__(16) float g_wa[KTOT];          // W @ a
__device__ float g_p[NEMAX];                        // emb[n] . wa[0:128]
__device__ float g_q[NEMAX];                        // emb[n] . wa[256:384]
__device__ float g_s[NRMAX];                        // rel[r] . wa[128:256]
__device__ float g_score[EMAX];                     // exp(score) per edge
__device__ float g_denom[NEMAX];                    // segment sum of exp
__device__ __align__(16) float g_acc[NEMAX * DD];   // emb@W1, then += scatter
__device__ __align__(16) __half g_embW3h[NEMAX * DD]; // emb@W3 (fp16)
__device__ __align__(16) __half g_relW2h[NRMAX * DD]; // rel@W2 (fp16)

// ---------- helpers ----------
__device__ __forceinline__ uint32_t f2tf(float f) {
    uint32_t r;
    asm("cvt.rna.tf32.f32 %0, %1;" : "=r"(r) : "f"(f));
    return r;
}

// ---------- small kernels ----------
__global__ void k_wa(const float* __restrict__ W, const float* __restrict__ a) {
    int k = blockIdx.x * blockDim.x + threadIdx.x;
    if (k < KTOT) {
        const float* row = W + (size_t)k * DD;
        float s = 0.f;
        #pragma unroll 8
        for (int u = 0; u < DD; u++) s = fmaf(row[u], a[u], s);
        g_wa[k] = s;
    }
}

__global__ void k_init(int NE) {
    int i = blockIdx.x * blockDim.x + threadIdx.x;
    if (i < NE) g_denom[i] = 0.f;
}

// single fused score pass: score -> exp -> denom accumulation (no max pass;
// exp(score)/sum(exp(score)) is identical to max-shifted softmax and scores
// are O(6) here, so no overflow)
__global__ void k_score(const int* __restrict__ h, const int* __restrict__ r,
                        const int* __restrict__ t, const float* __restrict__ ab, int E) {
    int e = blockIdx.x * blockDim.x + threadIdx.x;
    if (e >= E) return;
    int hn = h[e];
    float x = g_p[hn] + g_s[r[e]] + g_q[t[e]] + ab[0];
    float sc = x >= 0.f ? x : 0.04f * x;
    float ex = expf(sc);
    g_score[e] = ex;
    atomicAdd(&g_denom[hn], ex);
}

// relW2[r][u] = rel[r] . W2[:,u]  (W rows 128..255), stored fp16
// also computes s[r] = rel[r] . wa[128:256] (fused former k_rel_dots)
__global__ void k_relW2(const float* __restrict__ rel, const float* __restrict__ W, int NR) {
    __shared__ float sred[128];
    int rn = blockIdx.x;
    if (rn >= NR) return;
    int u = threadIdx.x;
    const float* rrow = rel + (size_t)rn * DD;
    float rv = rrow[u];
    // s reduction
    sred[u] = rv * g_wa[128 + u];
    __syncthreads();
    if (u < 64) sred[u] += sred[u + 64];
    __syncthreads();
    if (u < 32) {
        float v = sred[u] + sred[u + 32];
        #pragma unroll
        for (int o = 16; o; o >>= 1) v += __shfl_xor_sync(0xffffffffu, v, o);
        if (u == 0) g_s[rn] = v;
    }
    // relW2 row
    float s = 0.f;
    #pragma unroll 8
    for (int k = 0; k < DD; k++) s = fmaf(rrow[k], W[(size_t)(128 + k) * DD + u], s);
    g_relW2h[rn * DD + u] = __float2half_rn(s);
}

// ---------- tf32 tensor-core GEMM: [acc(f32) | embW3(f16)] = emb @ [W1 | W3] ----------
// also fused: p[n] = emb[n].wa[0:128], q[n] = emb[n].wa[256:384] in fp32
__global__ __launch_bounds__(256) void k_mm(const float* __restrict__ emb,
                                            const float* __restrict__ W, int NE) {
    __shared__ uint32_t As[64 * 36];
    __shared__ uint32_t Bs[32 * 264];
    int tid  = threadIdx.x;
    int lane = tid & 31;
    int wid  = tid >> 5;
    int g  = lane >> 2;
    int t4 = lane & 3;
    int wm = wid >> 2;
    int wn = wid & 3;
    int n0 = blockIdx.x * 64;
    int arow = tid >> 3;   // 0..31 (this thread's A row for i=0; +32 for i=1)
    int aq   = tid & 7;    // float4 slot within 32-k chunk

    float c[2][8][4];
    #pragma unroll
    for (int i = 0; i < 2; i++)
        #pragma unroll
        for (int j = 0; j < 8; j++)
            #pragma unroll
            for (int k = 0; k < 4; k++) c[i][j][k] = 0.f;

    float pp0 = 0.f, qq0 = 0.f, pp1 = 0.f, qq1 = 0.f;

    #pragma unroll 1
    for (int kc = 0; kc < 4; kc++) {
        int k0 = kc * 32;
        // wa segments this thread needs (same k range for both A rows)
        float4 wa0 = *(const float4*)&g_wa[k0 + aq * 4];
        float4 wa2 = *(const float4*)&g_wa[256 + k0 + aq * 4];
        #pragma unroll
        for (int i = 0; i < 2; i++) {
            int row = arow + i * 32;
            int n = n0 + row;
            float4 v = make_float4(0.f, 0.f, 0.f, 0.f);
            if (n < NE) v = *(const float4*)(emb + (size_t)n * DD + k0 + aq * 4);
            *(uint4*)&As[row * 36 + aq * 4] =
                make_uint4(f2tf(v.x), f2tf(v.y), f2tf(v.z), f2tf(v.w));
            float pd = v.x*wa0.x + v.y*wa0.y + v.z*wa0.z + v.w*wa0.w;
            float qd = v.x*wa2.x + v.y*wa2.y + v.z*wa2.z + v.w*wa2.w;
            if (i == 0) { pp0 += pd; qq0 += qd; }
            else        { pp1 += pd; qq1 += qd; }
        }
        #pragma unroll
        for (int i = 0; i < 8; i++) {
            int idx = tid + i * 256;
            int k  = idx >> 6;
            int u  = (idx & 63) * 4;
            const float* src = (u < 128)
                ? (W + (size_t)(k0 + k) * DD + u)
                : (W + (size_t)(256 + k0 + k) * DD + (u - 128));
            float4 v = *(const float4*)src;
            *(uint4*)&Bs[k * 264 + u] =
                make_uint4(f2tf(v.x), f2tf(v.y), f2tf(v.z), f2tf(v.w));
        }
        __syncthreads();
        #pragma unroll
        for (int ks = 0; ks < 4; ks++) {
            int kk = ks * 8;
            uint32_t a[2][4], b[8][2];
            #pragma unroll
            for (int fm = 0; fm < 2; fm++) {
                int mr = wm * 32 + fm * 16 + g;
                a[fm][0] = As[mr * 36 + kk + t4];
                a[fm][1] = As[(mr + 8) * 36 + kk + t4];
                a[fm][2] = As[mr * 36 + kk + t4 + 4];
                a[fm][3] = As[(mr + 8) * 36 + kk + t4 + 4];
            }
            #pragma unroll
            for (int fn = 0; fn < 8; fn++) {
                int col = wn * 64 + fn * 8 + g;
                b[fn][0] = Bs[(kk + t4) * 264 + col];
                b[fn][1] = Bs[(kk + t4 + 4) * 264 + col];
            }
            #pragma unroll
            for (int fm = 0; fm < 2; fm++)
                #pragma unroll
                for (int fn = 0; fn < 8; fn++)
                    asm volatile(
                        "mma.sync.aligned.m16n8k8.row.col.f32.tf32.tf32.f32 "
                        "{%0,%1,%2,%3}, {%4,%5,%6,%7}, {%8,%9}, {%0,%1,%2,%3};"
                        : "+f"(c[fm][fn][0]), "+f"(c[fm][fn][1]),
                          "+f"(c[fm][fn][2]), "+f"(c[fm][fn][3])
                        : "r"(a[fm][0]), "r"(a[fm][1]), "r"(a[fm][2]), "r"(a[fm][3]),
                          "r"(b[fn][0]), "r"(b[fn][1]));
        }
        __syncthreads();
    }

    // reduce p/q over the 8 threads sharing each A row (aligned 8-lane groups)
    #pragma unroll
    for (int o = 4; o; o >>= 1) {
        pp0 += __shfl_xor_sync(0xffffffffu, pp0, o);
        qq0 += __shfl_xor_sync(0xffffffffu, qq0, o);
        pp1 += __shfl_xor_sync(0xffffffffu, pp1, o);
        qq1 += __shfl_xor_sync(0xffffffffu, qq1, o);
    }
    if ((tid & 7) == 0) {
        int na = n0 + arow;
        if (na < NE)      { g_p[na] = pp0;      g_q[na] = qq0; }
        int nb = na + 32;
        if (nb < NE)      { g_p[nb] = pp1;      g_q[nb] = qq1; }
    }

    if (wn < 2) {
        // cols 0-127 of C -> g_acc fp32
        int colbase = wn * 64;
        #pragma unroll
        for (int fm = 0; fm < 2; fm++) {
            #pragma unroll
            for (int fn = 0; fn < 8; fn++) {
                int col = colbase + fn * 8 + t4 * 2;
                int r0 = n0 + wm * 32 + fm * 16 + g;
                if (r0 < NE)
                    *(float2*)&g_acc[(size_t)r0 * DD + col] =
                        make_float2(c[fm][fn][0], c[fm][fn][1]);
                int r1 = r0 + 8;
                if (r1 < NE)
                    *(float2*)&g_acc[(size_t)r1 * DD + col] =
                        make_float2(c[fm][fn][2], c[fm][fn][3]);
            }
        }
    } else {
        // cols 128-255 of C -> g_embW3h fp16
        int colbase = (wn - 2) * 64;
        #pragma unroll
        for (int fm = 0; fm < 2; fm++) {
            #pragma unroll
            for (int fn = 0; fn < 8; fn++) {
                int col = colbase + fn * 8 + t4 * 2;
                int r0 = n0 + wm * 32 + fm * 16 + g;
                if (r0 < NE)
                    *(__half2*)&g_embW3h[(size_t)r0 * DD + col] =
                        __floats2half2_rn(c[fm][fn][0], c[fm][fn][1]);
                int r1 = r0 + 8;
                if (r1 < NE)
                    *(__half2*)&g_embW3h[(size_t)r1 * DD + col] =
                        __floats2half2_rn(c[fm][fn][2], c[fm][fn][3]);
            }
        }
    }
}

// one warp per edge: acc[h] += alpha * (relW2[r] + embW3[t]); fp16 gathers, fp32 RED
__global__ __launch_bounds__(256) void k_scatter(const int* __restrict__ h,
                                                 const int* __restrict__ r,
                                                 const int* __restrict__ t, int E) {
    int e = (blockIdx.x * blockDim.x + threadIdx.x) >> 5;
    int lane = threadIdx.x & 31;
    if (e >= E) return;
    int hn = h[e], rn = r[e], tn = t[e];
    float sc = g_score[e];
    float dn = g_denom[hn];
    // 4 halves per lane from each table via one 8B load (coalesced 256B/row)
    uint2 ru = ((const uint2*)(g_relW2h + (size_t)rn * DD))[lane];
    uint2 tu = ((const uint2*)(g_embW3h + (size_t)tn * DD))[lane];
    float alpha = sc / dn;
    float2 fr0 = __half22float2(*(__half2*)&ru.x), fr1 = __half22float2(*(__half2*)&ru.y);
    float2 ft0 = __half22float2(*(__half2*)&tu.x), ft1 = __half22float2(*(__half2*)&tu.y);
    float4* dst = ((float4*)g_acc) + (size_t)hn * 32 + lane;
    atomicAdd(dst, make_float4(alpha * (fr0.x + ft0.x), alpha * (fr0.y + ft0.y),
                               alpha * (fr1.x + ft1.x), alpha * (fr1.y + ft1.y)));
}

// out[n] = relu(mask(n) * acc[n] + bias)
__global__ void k_out(const float* __restrict__ bias, float* __restrict__ out, int NE) {
    int idx = blockIdx.x * blockDim.x + threadIdx.x;
    if (idx >= NE * 32) return;
    int n = idx >> 5, u4 = idx & 31;
    float m = g_denom[n] > 0.f ? 1.f : 0.f;
    float4 a = ((const float4*)g_acc)[idx];
    float4 b = ((const float4*)bias)[u4];
    float4 o;
    o.x = fmaxf(fmaf(a.x, m, b.x), 0.f);
    o.y = fmaxf(fmaf(a.y, m, b.y), 0.f);
    o.z = fmaxf(fmaf(a.z, m, b.z), 0.f);
    o.w = fmaxf(fmaf(a.w, m, b.w), 0.f);
    ((float4*)out)[idx] = o;
}

extern "C" void kernel_launch(void* const* d_in, const int* in_sizes, int n_in,
                              void* d_out, int out_size) {
    const int*   h    = (const int*)d_in[0];
    const int*   r    = (const int*)d_in[1];
    const int*   t    = (const int*)d_in[2];
    const float* emb  = (const float*)d_in[3];
    const float* rel  = (const float*)d_in[4];
    const float* W    = (const float*)d_in[5];
    const float* a    = (const float*)d_in[6];
    const float* ab   = (const float*)d_in[7];
    const float* bias = (const float*)d_in[8];
    float* out = (float*)d_out;

    int E  = in_sizes[0];
    int NE = in_sizes[3] / DD;
    int NR = in_sizes[4] / DD;

    k_wa<<<2, 256>>>(W, a);
    k_init<<<(NE + 255) / 256, 256>>>(NE);
    k_mm<<<(NE + 63) / 64, 256>>>(emb, W, NE);
    k_relW2<<<NR, 128>>>(rel, W, NR);
    k_score<<<(E + 255) / 256, 256>>>(h, r, t, ab, E);
    k_scatter<<<(E * 32 + 255) / 256, 256>>>(h, r, t, E);
    k_out<<<(NE * 32 + 255) / 256, 256>>>(bias, out, NE);
}

// round 10
// speedup vs baseline: 1.2970x; 1.0316x over previous
#include <cuda_runtime.h>
#include <cuda_fp16.h>
#include <math.h>
#include <stdint.h>

// Problem constants (fixed by setup_inputs)
#define EMAX 500000
#define NEMAX 100000
#define NRMAX 1008
#define DD 128
#define KTOT 384

// ---------- device scratch (static; no allocation allowed) ----------
__device__ __align__(16) float g_wa[KTOT];          // W @ a
__device__ float g_p[NEMAX];                        // emb[n] . wa[0:128]
__device__ float g_q[NEMAX];                        // emb[n] . wa[256:384]
__device__ float g_s[NRMAX];                        // rel[r] . wa[128:256]
__device__ float g_score[EMAX];                     // exp(score) per edge
__device__ float g_denom[NEMAX];                    // segment sum of exp
__device__ __align__(16) float g_acc[NEMAX * DD];   // emb@W1, then += scatter
__device__ __align__(16) __half g_embW3h[NEMAX * DD]; // emb@W3 (fp16)
__device__ __align__(16) __half g_relW2h[NRMAX * DD]; // rel@W2 (fp16)

// ---------- helpers ----------
__device__ __forceinline__ uint32_t f2tf(float f) {
    uint32_t r;
    asm("cvt.rna.tf32.f32 %0, %1;" : "=r"(r) : "f"(f));
    return r;
}

// ---------- fused prep: g_wa = W@a (threads<384), g_denom=0 (threads<NE) ----------
__global__ void k_prep(const float* __restrict__ W, const float* __restrict__ a, int NE) {
    int i = blockIdx.x * blockDim.x + threadIdx.x;
    if (i < KTOT) {
        const float* row = W + (size_t)i * DD;
        float s0 = 0.f, s1 = 0.f, s2 = 0.f, s3 = 0.f;
        #pragma unroll
        for (int u = 0; u < DD; u += 4) {
            s0 = fmaf(row[u],     a[u],     s0);
            s1 = fmaf(row[u + 1], a[u + 1], s1);
            s2 = fmaf(row[u + 2], a[u + 2], s2);
            s3 = fmaf(row[u + 3], a[u + 3], s3);
        }
        g_wa[i] = (s0 + s1) + (s2 + s3);
    }
    if (i < NE) g_denom[i] = 0.f;
}

// single fused score pass: score -> exp -> denom accumulation (no max pass;
// exp(score)/sum(exp(score)) is identical to max-shifted softmax and scores
// are O(6) here, so no overflow)
__global__ void k_score(const int* __restrict__ h, const int* __restrict__ r,
                        const int* __restrict__ t, const float* __restrict__ ab, int E) {
    int e = blockIdx.x * blockDim.x + threadIdx.x;
    if (e >= E) return;
    int hn = h[e];
    float x = g_p[hn] + g_s[r[e]] + g_q[t[e]] + ab[0];
    float sc = x >= 0.f ? x : 0.04f * x;
    float ex = expf(sc);
    g_score[e] = ex;
    atomicAdd(&g_denom[hn], ex);
}

// relW2[r][u] = rel[r] . W2[:,u]  (W rows 128..255), stored fp16
// also computes s[r] = rel[r] . wa[128:256] (fused former k_rel_dots).
// rel row staged in shared; 4 independent accumulators break the fma chain.
__global__ __launch_bounds__(128) void k_relW2(const float* __restrict__ rel,
                                               const float* __restrict__ W, int NR) {
    __shared__ float srel[DD];
    __shared__ float sred[DD];
    int rn = blockIdx.x;
    if (rn >= NR) return;
    int u = threadIdx.x;
    float rv = rel[(size_t)rn * DD + u];
    srel[u] = rv;
    sred[u] = rv * g_wa[128 + u];
    __syncthreads();
    // s reduction
    if (u < 64) sred[u] += sred[u + 64];
    __syncthreads();
    if (u < 32) {
        float v = sred[u] + sred[u + 32];
        #pragma unroll
        for (int o = 16; o; o >>= 1) v += __shfl_xor_sync(0xffffffffu, v, o);
        if (u == 0) g_s[rn] = v;
    }
    // relW2 row: 4 independent accumulators, W loads batched by unroll
    const float* wcol = W + (size_t)128 * DD + u;
    float s0 = 0.f, s1 = 0.f, s2 = 0.f, s3 = 0.f;
    #pragma unroll
    for (int k = 0; k < DD; k += 4) {
        s0 = fmaf(srel[k],     wcol[(size_t)k * DD],       s0);
        s1 = fmaf(srel[k + 1], wcol[(size_t)(k + 1) * DD], s1);
        s2 = fmaf(srel[k + 2], wcol[(size_t)(k + 2) * DD], s2);
        s3 = fmaf(srel[k + 3], wcol[(size_t)(k + 3) * DD], s3);
    }
    g_relW2h[rn * DD + u] = __float2half_rn((s0 + s1) + (s2 + s3));
}

// ---------- tf32 tensor-core GEMM: [acc(f32) | embW3(f16)] = emb @ [W1 | W3] ----------
// also fused: p[n] = emb[n].wa[0:128], q[n] = emb[n].wa[256:384] in fp32
__global__ __launch_bounds__(256) void k_mm(const float* __restrict__ emb,
                                            const float* __restrict__ W, int NE) {
    __shared__ uint32_t As[64 * 36];
    __shared__ uint32_t Bs[32 * 264];
    int tid  = threadIdx.x;
    int lane = tid & 31;
    int wid  = tid >> 5;
    int g  = lane >> 2;
    int t4 = lane & 3;
    int wm = wid >> 2;
    int wn = wid & 3;
    int n0 = blockIdx.x * 64;
    int arow = tid >> 3;   // 0..31 (this thread's A row for i=0; +32 for i=1)
    int aq   = tid & 7;    // float4 slot within 32-k chunk

    float c[2][8][4];
    #pragma unroll
    for (int i = 0; i < 2; i++)
        #pragma unroll
        for (int j = 0; j < 8; j++)
            #pragma unroll
            for (int k = 0; k < 4; k++) c[i][j][k] = 0.f;

    float pp0 = 0.f, qq0 = 0.f, pp1 = 0.f, qq1 = 0.f;

    #pragma unroll 1
    for (int kc = 0; kc < 4; kc++) {
        int k0 = kc * 32;
        float4 wa0 = *(const float4*)&g_wa[k0 + aq * 4];
        float4 wa2 = *(const float4*)&g_wa[256 + k0 + aq * 4];
        #pragma unroll
        for (int i = 0; i < 2; i++) {
            int row = arow + i * 32;
            int n = n0 + row;
            float4 v = make_float4(0.f, 0.f, 0.f, 0.f);
            if (n < NE) v = *(const float4*)(emb + (size_t)n * DD + k0 + aq * 4);
            *(uint4*)&As[row * 36 + aq * 4] =
                make_uint4(f2tf(v.x), f2tf(v.y), f2tf(v.z), f2tf(v.w));
            float pd = v.x*wa0.x + v.y*wa0.y + v.z*wa0.z + v.w*wa0.w;
            float qd = v.x*wa2.x + v.y*wa2.y + v.z*wa2.z + v.w*wa2.w;
            if (i == 0) { pp0 += pd; qq0 += qd; }
            else        { pp1 += pd; qq1 += qd; }
        }
        #pragma unroll
        for (int i = 0; i < 8; i++) {
            int idx = tid + i * 256;
            int k  = idx >> 6;
            int u  = (idx & 63) * 4;
            const float* src = (u < 128)
                ? (W + (size_t)(k0 + k) * DD + u)
                : (W + (size_t)(256 + k0 + k) * DD + (u - 128));
            float4 v = *(const float4*)src;
            *(uint4*)&Bs[k * 264 + u] =
                make_uint4(f2tf(v.x), f2tf(v.y), f2tf(v.z), f2tf(v.w));
        }
        __syncthreads();
        #pragma unroll
        for (int ks = 0; ks < 4; ks++) {
            int kk = ks * 8;
            uint32_t a[2][4], b[8][2];
            #pragma unroll
            for (int fm = 0; fm < 2; fm++) {
                int mr = wm * 32 + fm * 16 + g;
                a[fm][0] = As[mr * 36 + kk + t4];
                a[fm][1] = As[(mr + 8) * 36 + kk + t4];
                a[fm][2] = As[mr * 36 + kk + t4 + 4];
                a[fm][3] = As[(mr + 8) * 36 + kk + t4 + 4];
            }
            #pragma unroll
            for (int fn = 0; fn < 8; fn++) {
                int col = wn * 64 + fn * 8 + g;
                b[fn][0] = Bs[(kk + t4) * 264 + col];
                b[fn][1] = Bs[(kk + t4 + 4) * 264 + col];
            }
            #pragma unroll
            for (int fm = 0; fm < 2; fm++)
                #pragma unroll
                for (int fn = 0; fn < 8; fn++)
                    asm volatile(
                        "mma.sync.aligned.m16n8k8.row.col.f32.tf32.tf32.f32 "
                        "{%0,%1,%2,%3}, {%4,%5,%6,%7}, {%8,%9}, {%0,%1,%2,%3};"
                        : "+f"(c[fm][fn][0]), "+f"(c[fm][fn][1]),
                          "+f"(c[fm][fn][2]), "+f"(c[fm][fn][3])
                        : "r"(a[fm][0]), "r"(a[fm][1]), "r"(a[fm][2]), "r"(a[fm][3]),
                          "r"(b[fn][0]), "r"(b[fn][1]));
        }
        __syncthreads();
    }

    // reduce p/q over the 8 threads sharing each A row (aligned 8-lane groups)
    #pragma unroll
    for (int o = 4; o; o >>= 1) {
        pp0 += __shfl_xor_sync(0xffffffffu, pp0, o);
        qq0 += __shfl_xor_sync(0xffffffffu, qq0, o);
        pp1 += __shfl_xor_sync(0xffffffffu, pp1, o);
        qq1 += __shfl_xor_sync(0xffffffffu, qq1, o);
    }
    if ((tid & 7) == 0) {
        int na = n0 + arow;
        if (na < NE)      { g_p[na] = pp0;      g_q[na] = qq0; }
        int nb = na + 32;
        if (nb < NE)      { g_p[nb] = pp1;      g_q[nb] = qq1; }
    }

    if (wn < 2) {
        int colbase = wn * 64;
        #pragma unroll
        for (int fm = 0; fm < 2; fm++) {
            #pragma unroll
            for (int fn = 0; fn < 8; fn++) {
                int col = colbase + fn * 8 + t4 * 2;
                int r0 = n0 + wm * 32 + fm * 16 + g;
                if (r0 < NE)
                    *(float2*)&g_acc[(size_t)r0 * DD + col] =
                        make_float2(c[fm][fn][0], c[fm][fn][1]);
                int r1 = r0 + 8;
                if (r1 < NE)
                    *(float2*)&g_acc[(size_t)r1 * DD + col] =
                        make_float2(c[fm][fn][2], c[fm][fn][3]);
            }
        }
    } else {
        int colbase = (wn - 2) * 64;
        #pragma unroll
        for (int fm = 0; fm < 2; fm++) {
            #pragma unroll
            for (int fn = 0; fn < 8; fn++) {
                int col = colbase + fn * 8 + t4 * 2;
                int r0 = n0 + wm * 32 + fm * 16 + g;
                if (r0 < NE)
                    *(__half2*)&g_embW3h[(size_t)r0 * DD + col] =
                        __floats2half2_rn(c[fm][fn][0], c[fm][fn][1]);
                int r1 = r0 + 8;
                if (r1 < NE)
                    *(__half2*)&g_embW3h[(size_t)r1 * DD + col] =
                        __floats2half2_rn(c[fm][fn][2], c[fm][fn][3]);
            }
        }
    }
}

// one warp per edge: acc[h] += alpha * (relW2[r] + embW3[t]); fp16 gathers, fp32 RED
__global__ __launch_bounds__(256) void k_scatter(const int* __restrict__ h,
                                                 const int* __restrict__ r,
                                                 const int* __restrict__ t, int E) {
    int e = (blockIdx.x * blockDim.x + threadIdx.x) >> 5;
    int lane = threadIdx.x & 31;
    if (e >= E) return;
    int hn = h[e], rn = r[e], tn = t[e];
    float sc = g_score[e];
    float dn = g_denom[hn];
    uint2 ru = ((const uint2*)(g_relW2h + (size_t)rn * DD))[lane];
    uint2 tu = ((const uint2*)(g_embW3h + (size_t)tn * DD))[lane];
    float alpha = sc / dn;
    float2 fr0 = __half22float2(*(__half2*)&ru.x), fr1 = __half22float2(*(__half2*)&ru.y);
    float2 ft0 = __half22float2(*(__half2*)&tu.x), ft1 = __half22float2(*(__half2*)&tu.y);
    float4* dst = ((float4*)g_acc) + (size_t)hn * 32 + lane;
    atomicAdd(dst, make_float4(alpha * (fr0.x + ft0.x), alpha * (fr0.y + ft0.y),
                               alpha * (fr1.x + ft1.x), alpha * (fr1.y + ft1.y)));
}

// out[n] = relu(mask(n) * acc[n] + bias)
__global__ void k_out(const float* __restrict__ bias, float* __restrict__ out, int NE) {
    int idx = blockIdx.x * blockDim.x + threadIdx.x;
    if (idx >= NE * 32) return;
    int n = idx >> 5, u4 = idx & 31;
    float m = g_denom[n] > 0.f ? 1.f : 0.f;
    float4 a = ((const float4*)g_acc)[idx];
    float4 b = ((const float4*)bias)[u4];
    float4 o;
    o.x = fmaxf(fmaf(a.x, m, b.x), 0.f);
    o.y = fmaxf(fmaf(a.y, m, b.y), 0.f);
    o.z = fmaxf(fmaf(a.z, m, b.z), 0.f);
    o.w = fmaxf(fmaf(a.w, m, b.w), 0.f);
    ((float4*)out)[idx] = o;
}

extern "C" void kernel_launch(void* const* d_in, const int* in_sizes, int n_in,
                              void* d_out, int out_size) {
    const int*   h    = (const int*)d_in[0];
    const int*   r    = (const int*)d_in[1];
    const int*   t    = (const int*)d_in[2];
    const float* emb  = (const float*)d_in[3];
    const float* rel  = (const float*)d_in[4];
    const float* W    = (const float*)d_in[5];
    const float* a    = (const float*)d_in[6];
    const float* ab   = (const float*)d_in[7];
    const float* bias = (const float*)d_in[8];
    float* out = (float*)d_out;

    int E  = in_sizes[0];
    int NE = in_sizes[3] / DD;
    int NR = in_sizes[4] / DD;

    k_prep<<<(NE + 255) / 256, 256>>>(W, a, NE);
    k_mm<<<(NE + 63) / 64, 256>>>(emb, W, NE);
    k_relW2<<<NR, 128>>>(rel, W, NR);
    k_score<<<(E + 255) / 256, 256>>>(h, r, t, ab, E);
    k_scatter<<<(E * 32 + 255) / 256, 256>>>(h, r, t, E);
    k_out<<<(NE * 32 + 255) / 256, 256>>>(bias, out, NE);
}